// round 10
// baseline (speedup 1.0000x reference)
#include <cuda_runtime.h>

// MomentumLIF: x[N,T,D] f32 -> spikes[N,T,D] f32
//   v_t = mom*v + x_t - lamb*u
//   u_t = 0.5*u + v_t        (decay = 1 - 1/tau, tau=2)
//   s_t = (u_t >= 1);  u_t = 0 if spiked (hard reset)
// One thread = 4 consecutive d (float4), serial over T=64 with u/v in regs.
// R9: partial L2 pinning of x across graph replays. R7 (fraction=1.0)
// thrashes: 128MB of evict_last lines > 126MB L2, zero reuse. Fraction=0.5
// pins ~64MB of x (hash-selected lines), which fits in L2 alongside the
// streaming remainder and the write-combined out buffer. Steady-state DRAM
// per replay: ~64MB reads + writes instead of 128MB reads + writes.
// Stores stay PLAIN (R8 proved .cs costs ~4-7us on bench by forcing
// writeback every replay).

#define LIF_N 64
#define LIF_T 64
#define LIF_D 8192
#define LIF_D4 (LIF_D / 4)          // 2048 float4 per row
#define THREADS 256
#define PF 6                        // prefetch depth

// float4 load with an L2 cache-hint policy.
__device__ __forceinline__ float4 ld_hint4(const float4* p,
                                           unsigned long long policy) {
    float4 v;
    asm("ld.global.L2::cache_hint.v4.f32 {%0,%1,%2,%3}, [%4], %5;"
        : "=f"(v.x), "=f"(v.y), "=f"(v.z), "=f"(v.w)
        : "l"(p), "l"(policy));
    return v;
}

__global__ __launch_bounds__(THREADS)
void momentum_lif_kernel(const float4* __restrict__ x,
                         const float* __restrict__ p_mom,
                         const float* __restrict__ p_lamb,
                         float4* __restrict__ out) {
    const float mom = __ldg(p_mom);
    const float lb  = __ldg(p_lamb);

    // Pin ~half of x's cache lines in L2 (evict_last); rest stream normally.
    unsigned long long policy;
    asm("createpolicy.fractional.L2::evict_last.b64 %0, 0.5;" : "=l"(policy));

    int idx = blockIdx.x * THREADS + threadIdx.x;   // 0 .. N*D4-1 (exact grid)
    int n  = idx >> 11;          // idx / 2048
    int d4 = idx & 2047;         // idx % 2048

    const float4* xp = x   + (size_t)n * LIF_T * LIF_D4 + d4;
    float4*       op = out + (size_t)n * LIF_T * LIF_D4 + d4;

    float ux = 0.f, uy = 0.f, uz = 0.f, uw = 0.f;
    float vx = 0.f, vy = 0.f, vz = 0.f, vw = 0.f;

    // Prime the pipeline: PF independent loads in flight before any compute.
    float4 buf[PF];
#pragma unroll
    for (int i = 0; i < PF; ++i)
        buf[i] = ld_hint4(xp + (size_t)i * LIF_D4, policy);

#pragma unroll
    for (int t = 0; t < LIF_T; ++t) {
        float4 xv = buf[t % PF];
        // Refill the slot before the dependent math so the load overlaps
        // this iteration's compute + store.
        if (t + PF < LIF_T)
            buf[t % PF] = ld_hint4(xp + (size_t)(t + PF) * LIF_D4, policy);

        // lane x
        vx = fmaf(mom, vx, xv.x);
        vx = fmaf(-lb, ux, vx);
        ux = fmaf(0.5f, ux, vx);
        float sx = (ux >= 1.0f) ? 1.0f : 0.0f;
        ux = (ux >= 1.0f) ? 0.0f : ux;
        // lane y
        vy = fmaf(mom, vy, xv.y);
        vy = fmaf(-lb, uy, vy);
        uy = fmaf(0.5f, uy, vy);
        float sy = (uy >= 1.0f) ? 1.0f : 0.0f;
        uy = (uy >= 1.0f) ? 0.0f : uy;
        // lane z
        vz = fmaf(mom, vz, xv.z);
        vz = fmaf(-lb, uz, vz);
        uz = fmaf(0.5f, uz, vz);
        float sz = (uz >= 1.0f) ? 1.0f : 0.0f;
        uz = (uz >= 1.0f) ? 0.0f : uz;
        // lane w
        vw = fmaf(mom, vw, xv.w);
        vw = fmaf(-lb, uw, vw);
        uw = fmaf(0.5f, uw, vw);
        float sw = (uw >= 1.0f) ? 1.0f : 0.0f;
        uw = (uw >= 1.0f) ? 0.0f : uw;

        op[(size_t)t * LIF_D4] = make_float4(sx, sy, sz, sw);  // plain store
    }
}

extern "C" void kernel_launch(void* const* d_in, const int* in_sizes, int n_in,
                              void* d_out, int out_size) {
    const float4* x      = (const float4*)d_in[0];
    const float*  p_mom  = (const float*)d_in[1];
    const float*  p_lamb = (const float*)d_in[2];
    float4*       out    = (float4*)d_out;

    const int total = LIF_N * LIF_D4;           // 131072 threads
    momentum_lif_kernel<<<total / THREADS, THREADS>>>(x, p_mom, p_lamb, out);
}

// round 11
// speedup vs baseline: 1.0558x; 1.0558x over previous
#include <cuda_runtime.h>

// MomentumLIF: x[N,T,D] f32 -> spikes[N,T,D] f32
//   v_t = mom*v + x_t - lamb*u
//   u_t = 0.5*u + v_t        (decay = 1 - 1/tau, tau=2)
//   s_t = (u_t >= 1);  u_t = 0 if spiked (hard reset)
// R10: float2 decomposition -> 262144 threads (2x R8) for latency hiding.
// Cache policy: PLAIN loads + PLAIN stores (R2/R7/R9 proved every hint
// variant loses to default replacement for this 256MB cyclic working set).
// Depth-6 prefetch pipeline per thread; same total bytes in flight as R8
// but twice the warps to cover the dependent FMA-chain bubbles.

#define LIF_N 64
#define LIF_T 64
#define LIF_D 8192
#define LIF_D2 (LIF_D / 2)          // 4096 float2 per row
#define THREADS 256
#define PF 6                        // prefetch depth

__global__ __launch_bounds__(THREADS)
void momentum_lif_kernel(const float2* __restrict__ x,
                         const float* __restrict__ p_mom,
                         const float* __restrict__ p_lamb,
                         float2* __restrict__ out) {
    const float mom = __ldg(p_mom);
    const float lb  = __ldg(p_lamb);

    int idx = blockIdx.x * THREADS + threadIdx.x;   // 0 .. N*D2-1 (exact grid)
    int n  = idx >> 12;          // idx / 4096
    int d2 = idx & 4095;         // idx % 4096

    const float2* xp = x   + (size_t)n * LIF_T * LIF_D2 + d2;
    float2*       op = out + (size_t)n * LIF_T * LIF_D2 + d2;

    float ux = 0.f, uy = 0.f;
    float vx = 0.f, vy = 0.f;

    // Prime the pipeline: PF independent loads in flight before any compute.
    float2 buf[PF];
#pragma unroll
    for (int i = 0; i < PF; ++i)
        buf[i] = xp[(size_t)i * LIF_D2];

#pragma unroll
    for (int t = 0; t < LIF_T; ++t) {
        float2 xv = buf[t % PF];
        // Refill the slot before the dependent math so the load overlaps
        // this iteration's compute + store.
        if (t + PF < LIF_T)
            buf[t % PF] = xp[(size_t)(t + PF) * LIF_D2];

        // lane x
        vx = fmaf(mom, vx, xv.x);
        vx = fmaf(-lb, ux, vx);
        ux = fmaf(0.5f, ux, vx);
        float sx = (ux >= 1.0f) ? 1.0f : 0.0f;
        ux = (ux >= 1.0f) ? 0.0f : ux;
        // lane y
        vy = fmaf(mom, vy, xv.y);
        vy = fmaf(-lb, uy, vy);
        uy = fmaf(0.5f, uy, vy);
        float sy = (uy >= 1.0f) ? 1.0f : 0.0f;
        uy = (uy >= 1.0f) ? 0.0f : uy;

        op[(size_t)t * LIF_D2] = make_float2(sx, sy);   // plain store
    }
}

extern "C" void kernel_launch(void* const* d_in, const int* in_sizes, int n_in,
                              void* d_out, int out_size) {
    const float2* x      = (const float2*)d_in[0];
    const float*  p_mom  = (const float*)d_in[1];
    const float*  p_lamb = (const float*)d_in[2];
    float2*       out    = (float2*)d_out;

    const int total = LIF_N * LIF_D2;           // 262144 threads
    momentum_lif_kernel<<<total / THREADS, THREADS>>>(x, p_mom, p_lamb, out);
}